// round 5
// baseline (speedup 1.0000x reference)
#include <cuda_runtime.h>
#include <cuda_fp16.h>
#include <stdint.h>
#include <math.h>

#define MTOT 16384
#define DIN  1024
#define DSZ  256
#define KCH  32            // k-halfs per pipeline chunk
#define LDR  80            // padded SMEM row stride in bytes (40 halfs)
#define NST  4

// gemm1 (512 thr): A 128 rows, B 256 rows
#define PLA1 (128 * LDR)
#define PLB1 (256 * LDR)
#define STG1 (PLA1 + PLB1)
#define SMEM1 (NST * STG1)      // 122880
// gemm2 (256 thr): A 128 rows, B 128 rows
#define PLA2 (128 * LDR)
#define STG2 (2 * PLA2)
#define SMEM2 (NST * STG2)      // 81920

// ---------------- scratch (__device__ globals; no allocations) ----------------
__device__ __half xh_g[(size_t)MTOT * DIN];
__device__ __half w1f16_g[(size_t)12 * DSZ * DIN];   // [mat*4+s][n=d][k]
__device__ __half w2f16_g[(size_t)4 * DSZ * DSZ];    // [s][n=e][k]
__device__ __half g1f16_g[(size_t)4 * MTOT * DSZ];
__device__ __half dre_g[(size_t)4 * MTOT * DSZ];
__device__ __half dim_g[(size_t)4 * MTOT * DSZ];
__device__ float omg_g[(size_t)4 * MTOT * DSZ];
__device__ float2 Aseg_g[256 * 256];
__device__ float2 Hseg_g[256 * 256];
__device__ float2 Ini_g [256 * 256];

// ---------------- PTX helpers (baseline ISA only) ------------------------------
__device__ __forceinline__ uint32_t smem_u32(const void* p) {
    uint32_t a;
    asm("{ .reg .u64 t; cvta.to.shared.u64 t, %1; cvt.u32.u64 %0, t; }" : "=r"(a) : "l"(p));
    return a;
}
__device__ __forceinline__ void cpa16(uint32_t dst, const void* src) {
    asm volatile("cp.async.cg.shared.global [%0], [%1], 16;" :: "r"(dst), "l"(src));
}
__device__ __forceinline__ void cpa_commit() {
    asm volatile("cp.async.commit_group;");
}
template<int N> __device__ __forceinline__ void cpa_wait() {
    asm volatile("cp.async.wait_group %0;" :: "n"(N));
}
__device__ __forceinline__ void ldsm4(uint32_t r[4], uint32_t addr) {
    asm volatile("ldmatrix.sync.aligned.m8n8.x4.shared.b16 {%0,%1,%2,%3}, [%4];"
        : "=r"(r[0]), "=r"(r[1]), "=r"(r[2]), "=r"(r[3]) : "r"(addr));
}
__device__ __forceinline__ void mma_f16(float c[4], const uint32_t a[4], const uint32_t b[2]) {
    asm volatile("mma.sync.aligned.m16n8k16.row.col.f32.f16.f16.f32 "
        "{%0,%1,%2,%3}, {%4,%5,%6,%7}, {%8,%9}, {%0,%1,%2,%3};"
        : "+f"(c[0]), "+f"(c[1]), "+f"(c[2]), "+f"(c[3])
        : "r"(a[0]), "r"(a[1]), "r"(a[2]), "r"(a[3]), "r"(b[0]), "r"(b[1]));
}

// ---------------- GEMM 1: C[128,256] = x[128,K] x W^T[256,K], 512 threads -------
__global__ __launch_bounds__(512, 1) void gemm1_k(
    const float* __restrict__ bg1, const float* __restrict__ bdr, const float* __restrict__ bdi)
{
    extern __shared__ char sm[];
    uint32_t s0 = smem_u32(sm);
    const int tid = threadIdx.x;

    const int mbase = blockIdx.x * 128;
    const int nb = blockIdx.y;                 // 0..11
    const int mat = nb >> 2;                   // 0=g1, 1=dre, 2=dim
    const int s = nb & 3;

    const __half* gA = xh_g + (size_t)mbase * DIN;
    const __half* gB = w1f16_g + (size_t)nb * DSZ * DIN;

    auto issue = [&](int st, int k0) {
        uint32_t base = s0 + st * STG1;
        {
            int r = tid >> 2, c = tid & 3;
            cpa16(base + r * LDR + c * 16, gA + (size_t)r * DIN + k0 + c * 8);
        }
#pragma unroll
        for (int it = 0; it < 2; it++) {
            int q = tid + it * 512;
            int r = q >> 2, c = q & 3;
            cpa16(base + PLA1 + r * LDR + c * 16, gB + (size_t)r * DIN + k0 + c * 8);
        }
        cpa_commit();
    };

    float acc[2][8][4];
#pragma unroll
    for (int i = 0; i < 2; i++)
#pragma unroll
        for (int j = 0; j < 8; j++)
#pragma unroll
            for (int k = 0; k < 4; k++) acc[i][j][k] = 0.f;

    constexpr int NCH = DIN / KCH;     // 32
    issue(0, 0);
    issue(1, KCH);
    issue(2, 2 * KCH);

    const int lane = tid & 31, warp = tid >> 5;
    const int wm = warp & 3, wn = warp >> 2;   // wn 0..3
    const uint32_t aBase = (uint32_t)(wm * 32 + (lane & 15)) * LDR + (lane >> 4) * 16;
    const uint32_t bBase = (uint32_t)(wn * 64 + (lane & 7) + ((lane & 16) >> 1)) * LDR
                         + ((lane >> 3) & 1) * 16;

    for (int ch = 0; ch < NCH; ch++) {
        if (ch >= NCH - 1)      cpa_wait<0>();
        else if (ch == NCH - 2) cpa_wait<1>();
        else                    cpa_wait<2>();
        __syncthreads();
        const uint32_t sb = s0 + (ch & (NST - 1)) * STG1;
        if (ch + 3 < NCH) issue((ch + 3) & (NST - 1), (ch + 3) * KCH);
#pragma unroll
        for (int ks = 0; ks < 2; ks++) {
            uint32_t ah[2][4], bb[4][4];
#pragma unroll
            for (int mi = 0; mi < 2; mi++)
                ldsm4(ah[mi], sb + aBase + mi * (16 * LDR) + ks * 32);
#pragma unroll
            for (int nf4 = 0; nf4 < 4; nf4++)
                ldsm4(bb[nf4], sb + PLA1 + bBase + nf4 * (16 * LDR) + ks * 32);
#pragma unroll
            for (int mi = 0; mi < 2; mi++)
#pragma unroll
                for (int nf = 0; nf < 8; nf++)
                    mma_f16(acc[mi][nf], ah[mi], &bb[nf >> 1][(nf & 1) * 2]);
        }
    }

    const int r0 = mbase + wm * 32 + (lane >> 2);
    const int c0 = wn * 64 + (lane & 3) * 2;
    const float* bias = (mat == 0 ? bg1 : (mat == 1 ? bdr : bdi)) + s * DSZ;
    __half* op = (mat == 0 ? g1f16_g : (mat == 1 ? dre_g : dim_g)) + (size_t)s * MTOT * DSZ;
    const bool rl = (mat == 0);

#pragma unroll
    for (int mi = 0; mi < 2; mi++)
#pragma unroll
        for (int nf = 0; nf < 8; nf++) {
            int col = c0 + nf * 8;
            float b0 = bias[col], b1 = bias[col + 1];
#pragma unroll
            for (int hh = 0; hh < 2; hh++) {
                int r = r0 + mi * 16 + hh * 8;
                float v0 = acc[mi][nf][hh * 2 + 0] + b0;
                float v1 = acc[mi][nf][hh * 2 + 1] + b1;
                if (rl) { v0 = fmaxf(v0, 0.f); v1 = fmaxf(v1, 0.f); }
                *(__half2*)(op + (size_t)r * DSZ + col) =
                    __halves2half2(__float2half_rn(v0), __float2half_rn(v1));
            }
        }
}

// ---------------- GEMM 2: omg = 1 - sigmoid(g1 @ Wg2 + bg2), 256 threads -------
__global__ __launch_bounds__(256) void gemm2_k(const float* __restrict__ bg2)
{
    extern __shared__ char sm[];
    uint32_t s0 = smem_u32(sm);
    const int tid = threadIdx.x;

    const int mbase = blockIdx.x * 128;
    const int s = blockIdx.y >> 1;
    const int dbase = (blockIdx.y & 1) * 128;

    const __half* gA = g1f16_g + ((size_t)s * MTOT + mbase) * DSZ;
    const __half* gB = w2f16_g + ((size_t)s * DSZ + dbase) * DSZ;

    auto issue = [&](int st, int k0) {
        uint32_t base = s0 + st * STG2;
#pragma unroll
        for (int it = 0; it < 2; it++) {
            int q = tid + it * 256;
            int r = q >> 2, c = q & 3;
            uint32_t off = base + r * LDR + c * 16;
            size_t go = (size_t)r * DSZ + k0 + c * 8;
            cpa16(off,         gA + go);
            cpa16(off + PLA2,  gB + go);
        }
        cpa_commit();
    };

    float acc[2][8][4];
#pragma unroll
    for (int i = 0; i < 2; i++)
#pragma unroll
        for (int j = 0; j < 8; j++)
#pragma unroll
            for (int k = 0; k < 4; k++) acc[i][j][k] = 0.f;

    constexpr int NCH = DSZ / KCH;     // 8
    issue(0, 0);
    issue(1, KCH);
    issue(2, 2 * KCH);

    const int lane = tid & 31, warp = tid >> 5;
    const int wm = warp & 3, wn = warp >> 2;   // wn 0..1
    const uint32_t aBase = (uint32_t)(wm * 32 + (lane & 15)) * LDR + (lane >> 4) * 16;
    const uint32_t bBase = (uint32_t)(wn * 64 + (lane & 7) + ((lane & 16) >> 1)) * LDR
                         + ((lane >> 3) & 1) * 16;

    for (int ch = 0; ch < NCH; ch++) {
        if (ch >= NCH - 1)      cpa_wait<0>();
        else if (ch == NCH - 2) cpa_wait<1>();
        else                    cpa_wait<2>();
        __syncthreads();
        const uint32_t sb = s0 + (ch & (NST - 1)) * STG2;
        if (ch + 3 < NCH) issue((ch + 3) & (NST - 1), (ch + 3) * KCH);
#pragma unroll
        for (int ks = 0; ks < 2; ks++) {
            uint32_t ah[2][4], bb[4][4];
#pragma unroll
            for (int mi = 0; mi < 2; mi++)
                ldsm4(ah[mi], sb + aBase + mi * (16 * LDR) + ks * 32);
#pragma unroll
            for (int nf4 = 0; nf4 < 4; nf4++)
                ldsm4(bb[nf4], sb + PLA2 + bBase + nf4 * (16 * LDR) + ks * 32);
#pragma unroll
            for (int mi = 0; mi < 2; mi++)
#pragma unroll
                for (int nf = 0; nf < 8; nf++)
                    mma_f16(acc[mi][nf], ah[mi], &bb[nf >> 1][(nf & 1) * 2]);
        }
    }

    const int r0 = mbase + wm * 32 + (lane >> 2);
    const int c0 = wn * 64 + (lane & 3) * 2;
    const float* bias = bg2 + s * DSZ + dbase;
    float* op = omg_g + (size_t)s * MTOT * DSZ;

#pragma unroll
    for (int mi = 0; mi < 2; mi++)
#pragma unroll
        for (int nf = 0; nf < 8; nf++) {
            int col = c0 + nf * 8;
            float b0 = bias[col], b1 = bias[col + 1];
#pragma unroll
            for (int hh = 0; hh < 2; hh++) {
                int r = r0 + mi * 16 + hh * 8;
                float2 v;
                v.x = 1.0f / (1.0f + expf(acc[mi][nf][hh * 2 + 0] + b0));
                v.y = 1.0f / (1.0f + expf(acc[mi][nf][hh * 2 + 1] + b1));
                *(float2*)(op + (size_t)r * DSZ + dbase + col) = v;
            }
        }
}

// ---------------- conversion kernels -------------------------------------------
__global__ __launch_bounds__(256) void conv_x_k(const float* __restrict__ x) {
    size_t i = ((size_t)blockIdx.x * 256 + threadIdx.x) * 4;
    float4 v = *(const float4*)(x + i);
    union { __half h[4]; uint2 u; } p;
    p.h[0] = __float2half_rn(v.x);
    p.h[1] = __float2half_rn(v.y);
    p.h[2] = __float2half_rn(v.z);
    p.h[3] = __float2half_rn(v.w);
    *(uint2*)(xh_g + i) = p.u;
}

__global__ void conv_w1_k(const float* __restrict__ src, int zbase, int kdim) {
    __shared__ float t[32][33];
    int z = blockIdx.z;
    const float* sp = src + (size_t)z * kdim * DSZ;
    int tx = threadIdx.x, ty = threadIdx.y;
    int k0 = blockIdx.x * 32, d0 = blockIdx.y * 32;
#pragma unroll
    for (int i = 0; i < 4; i++)
        t[ty + i * 8][tx] = sp[(size_t)(k0 + ty + i * 8) * DSZ + d0 + tx];
    __syncthreads();
    __half* oh = (kdim == DIN ? w1f16_g + (size_t)(zbase + z) * DSZ * DIN
                              : w2f16_g + (size_t)z * DSZ * DSZ);
#pragma unroll
    for (int i = 0; i < 4; i++) {
        int n = d0 + ty + i * 8, k = k0 + tx;
        oh[(size_t)n * kdim + k] = __float2half_rn(t[tx][ty + i * 8]);
    }
}

// ---------------- segmented scan (3 phases) ------------------------------------
struct ScanConsts { float abr[4], abi[4], bsc[4]; };

__global__ __launch_bounds__(256) void scan_p1(ScanConsts c) {
    const int idx = blockIdx.x;                 // b*64 + s*16 + seg
    const int seg = idx & 15, s = (idx >> 4) & 3, b = idx >> 6;
    const int d = threadIdx.x;
    const float abr = c.abr[s], abi = c.abi[s], bs = c.bsc[s];
    const size_t base = ((size_t)s * MTOT + (size_t)b * 4096 + seg * 256) * DSZ + d;
    float Ar = 1.f, Ai = 0.f, Hr = 0.f, Hi = 0.f;
#pragma unroll 4
    for (int t = 0; t < 256; t++) {
        size_t off = base + (size_t)t * DSZ;
        float w  = omg_g[off];
        float xr = __half2float(dre_g[off]);
        float xi = __half2float(dim_g[off]);
        float ar = w * abr, ai = w * abi, wb = w * bs;
        float br = wb * xr, bi = wb * xi;
        float nHr = fmaf(ar, Hr, fmaf(-ai, Hi, br));
        float nHi = fmaf(ar, Hi, fmaf( ai, Hr, bi));
        float nAr = fmaf(ar, Ar, -ai * Ai);
        float nAi = fmaf(ar, Ai,  ai * Ar);
        Hr = nHr; Hi = nHi; Ar = nAr; Ai = nAi;
    }
    Aseg_g[idx * 256 + d] = make_float2(Ar, Ai);
    Hseg_g[idx * 256 + d] = make_float2(Hr, Hi);
}

__global__ __launch_bounds__(256) void scan_p2() {
    const int bs_ = blockIdx.x;                 // b*4 + s
    const int d = threadIdx.x;
    float cr = 0.f, ci = 0.f;
#pragma unroll
    for (int g = 0; g < 16; g++) {
        int idx = (bs_ * 16 + g) * 256 + d;
        Ini_g[idx] = make_float2(cr, ci);
        float2 A = Aseg_g[idx];
        float2 H = Hseg_g[idx];
        float ncr = fmaf(A.x, cr, fmaf(-A.y, ci, H.x));
        float nci = fmaf(A.x, ci, fmaf( A.y, cr, H.y));
        cr = ncr; ci = nci;
    }
}

__global__ __launch_bounds__(256) void scan_p3(float* __restrict__ out, ScanConsts c) {
    const int idx = blockIdx.x;
    const int seg = idx & 15, s = (idx >> 4) & 3, b = idx >> 6;
    const int d = threadIdx.x;
    const float abr = c.abr[s], abi = c.abi[s], bs = c.bsc[s];
    const size_t base = ((size_t)s * MTOT + (size_t)b * 4096 + seg * 256) * DSZ + d;
    float2 h0 = Ini_g[idx * 256 + d];
    float hr = h0.x, hi = h0.y;
    float* op = out + ((size_t)b * 4096 + seg * 256) * 2048 + (size_t)s * 512 + d;
#pragma unroll 4
    for (int t = 0; t < 256; t++) {
        size_t off = base + (size_t)t * DSZ;
        float w  = omg_g[off];
        float xr = __half2float(dre_g[off]);
        float xi = __half2float(dim_g[off]);
        float ar = w * abr, ai = w * abi, wb = w * bs;
        float br = wb * xr, bi = wb * xi;
        float nhr = fmaf(ar, hr, fmaf(-ai, hi, br));
        float nhi = fmaf(ar, hi, fmaf( ai, hr, bi));
        hr = nhr; hi = nhi;
        op[(size_t)t * 2048]       = hr;
        op[(size_t)t * 2048 + 256] = hi;
    }
}

// ---------------- host ----------------------------------------------------------
extern "C" void kernel_launch(void* const* d_in, const int* in_sizes, int n_in,
                              void* d_out, int out_size)
{
    const float* x   = (const float*)d_in[0];
    const float* Wg1 = (const float*)d_in[1];
    const float* bg1 = (const float*)d_in[2];
    const float* Wg2 = (const float*)d_in[3];
    const float* bg2 = (const float*)d_in[4];
    const float* Wdr = (const float*)d_in[5];
    const float* bdr = (const float*)d_in[6];
    const float* Wdi = (const float*)d_in[7];
    const float* bdi = (const float*)d_in[8];
    float* out = (float*)d_out;

    cudaFuncSetAttribute(gemm1_k, cudaFuncAttributeMaxDynamicSharedMemorySize, SMEM1);
    cudaFuncSetAttribute(gemm2_k, cudaFuncAttributeMaxDynamicSharedMemorySize, SMEM2);

    conv_x_k<<<(int)(((size_t)MTOT * DIN) / 1024), 256>>>(x);
    dim3 tb(32, 8);
    conv_w1_k<<<dim3(32, 8, 4), tb>>>(Wg1, 0, DIN);
    conv_w1_k<<<dim3(32, 8, 4), tb>>>(Wdr, 4, DIN);
    conv_w1_k<<<dim3(32, 8, 4), tb>>>(Wdi, 8, DIN);
    conv_w1_k<<<dim3(8, 8, 4), tb>>>(Wg2, 0, DSZ);

    gemm1_k<<<dim3(MTOT / 128, 12), 512, SMEM1>>>(bg1, bdr, bdi);
    gemm2_k<<<dim3(MTOT / 128, 8), 256, SMEM2>>>(bg2);

    ScanConsts c;
    const double r [4] = {1.0, 0.999, 0.9495, 0.9};
    const double th[4] = {0.0, 0.01,  0.505,  1.0};
    for (int s = 0; s < 4; s++) {
        c.abr[s] = (float)(r[s] * cos(th[s]));
        c.abi[s] = (float)(r[s] * sin(th[s]));
        c.bsc[s] = (float)((r[s] >= 1.0) ? (1.0 / 16.0) : (1.0 - r[s]));
    }
    scan_p1<<<256, 256>>>(c);
    scan_p2<<<16, 256>>>();
    scan_p3<<<256, 256>>>(out, c);
}

// round 6
// speedup vs baseline: 1.1467x; 1.1467x over previous
#include <cuda_runtime.h>
#include <cuda_fp16.h>
#include <stdint.h>
#include <math.h>

#define MTOT 16384
#define DIN  1024
#define DSZ  256
#define KCH  32            // k-halfs per pipeline chunk
#define LDR  80            // padded SMEM row stride in bytes (40 halfs)
#define PL_A (128 * LDR)   // 10240 bytes per plane (128 rows)
#define STG  (2 * PL_A)    // A, B planes per stage
#define NST  4
#define SMEM_SZ (NST * STG)   // 81920 -> 2 CTAs/SM

// ---------------- scratch (__device__ globals; no allocations) ----------------
__device__ __half xh_g[(size_t)MTOT * DIN];
__device__ __half w1f16_g[(size_t)12 * DSZ * DIN];   // [mat*4+s][n=d][k]
__device__ __half w2f16_g[(size_t)4 * DSZ * DSZ];    // [s][n=e][k]
__device__ __half g1f16_g[(size_t)4 * MTOT * DSZ];
__device__ __half dre_g[(size_t)4 * MTOT * DSZ];
__device__ __half dim_g[(size_t)4 * MTOT * DSZ];
__device__ float omg_g[(size_t)4 * MTOT * DSZ];
__device__ float2 Aseg_g[256 * 256];
__device__ float2 Hseg_g[256 * 256];
__device__ float2 Ini_g [256 * 256];

// ---------------- PTX helpers (baseline ISA only) ------------------------------
__device__ __forceinline__ uint32_t smem_u32(const void* p) {
    uint32_t a;
    asm("{ .reg .u64 t; cvta.to.shared.u64 t, %1; cvt.u32.u64 %0, t; }" : "=r"(a) : "l"(p));
    return a;
}
__device__ __forceinline__ void cpa16(uint32_t dst, const void* src) {
    asm volatile("cp.async.cg.shared.global [%0], [%1], 16;" :: "r"(dst), "l"(src));
}
__device__ __forceinline__ void cpa_commit() {
    asm volatile("cp.async.commit_group;");
}
template<int N> __device__ __forceinline__ void cpa_wait() {
    asm volatile("cp.async.wait_group %0;" :: "n"(N));
}
__device__ __forceinline__ void ldsm4(uint32_t r[4], uint32_t addr) {
    asm volatile("ldmatrix.sync.aligned.m8n8.x4.shared.b16 {%0,%1,%2,%3}, [%4];"
        : "=r"(r[0]), "=r"(r[1]), "=r"(r[2]), "=r"(r[3]) : "r"(addr));
}
__device__ __forceinline__ void mma_f16(float c[4], const uint32_t a[4], const uint32_t b[2]) {
    asm volatile("mma.sync.aligned.m16n8k16.row.col.f32.f16.f16.f32 "
        "{%0,%1,%2,%3}, {%4,%5,%6,%7}, {%8,%9}, {%0,%1,%2,%3};"
        : "+f"(c[0]), "+f"(c[1]), "+f"(c[2]), "+f"(c[3])
        : "r"(a[0]), "r"(a[1]), "r"(a[2]), "r"(a[3]), "r"(b[0]), "r"(b[1]));
}

// ---------------- GEMM pipeline core (R4 geometry, single barrier) --------------
// C[128,128] = A[128,K] x B^T[128,K], fp32 accum, 8 warps (4m x 2n), 3-deep prefetch.
template<int NCH>
__device__ __forceinline__ void gemm_pipeline(
    const __half* __restrict__ gA, const __half* __restrict__ gB,
    const int ldk, uint32_t s0, float acc[2][8][4])
{
    const int tid = threadIdx.x;

    auto issue = [&](int st, int k0) {
        uint32_t base = s0 + st * STG;
#pragma unroll
        for (int it = 0; it < 2; it++) {
            int q = tid + it * 256;
            int r = q >> 2, c = q & 3;
            uint32_t off = base + r * LDR + c * 16;
            size_t go = (size_t)r * ldk + k0 + c * 8;
            cpa16(off,        gA + go);
            cpa16(off + PL_A, gB + go);
        }
        cpa_commit();
    };

#pragma unroll
    for (int i = 0; i < 2; i++)
#pragma unroll
        for (int j = 0; j < 8; j++)
#pragma unroll
            for (int k = 0; k < 4; k++) acc[i][j][k] = 0.f;

    issue(0, 0);
    if (NCH > 1) issue(1, KCH);
    if (NCH > 2) issue(2, 2 * KCH);

    const int lane = tid & 31, warp = tid >> 5;
    const int wm = warp & 3, wn = warp >> 2;
    const uint32_t aBase = (uint32_t)(wm * 32 + (lane & 15)) * LDR + (lane >> 4) * 16;
    const uint32_t bBase = (uint32_t)(wn * 64 + (lane & 7) + ((lane & 16) >> 1)) * LDR
                         + ((lane >> 3) & 1) * 16;

    for (int ch = 0; ch < NCH; ch++) {
        if (ch >= NCH - 1)      cpa_wait<0>();
        else if (ch == NCH - 2) cpa_wait<1>();
        else                    cpa_wait<2>();
        __syncthreads();   // orders prev-iter reads before overwrite of stage (ch-1)&3
        const uint32_t sb = s0 + (ch & (NST - 1)) * STG;
        if (ch + 3 < NCH) issue((ch + 3) & (NST - 1), (ch + 3) * KCH);
#pragma unroll
        for (int ks = 0; ks < 2; ks++) {
            uint32_t ah[2][4], bb[4][4];
#pragma unroll
            for (int mi = 0; mi < 2; mi++)
                ldsm4(ah[mi], sb + aBase + mi * (16 * LDR) + ks * 32);
#pragma unroll
            for (int nf4 = 0; nf4 < 4; nf4++)
                ldsm4(bb[nf4], sb + PL_A + bBase + nf4 * (16 * LDR) + ks * 32);
#pragma unroll
            for (int mi = 0; mi < 2; mi++)
#pragma unroll
                for (int nf = 0; nf < 8; nf++)
                    mma_f16(acc[mi][nf], ah[mi], &bb[nf >> 1][(nf & 1) * 2]);
        }
    }
}

// ---------------- GEMM 1: x @ {Wg1,Wdr,Wdi} -----------------------------------
__global__ __launch_bounds__(256) void gemm1_k(
    const float* __restrict__ bg1, const float* __restrict__ bdr, const float* __restrict__ bdi)
{
    extern __shared__ char sm[];
    uint32_t s0 = smem_u32(sm);

    const int mbase = blockIdx.x * 128;
    const int nb = blockIdx.y;                 // 0..23
    const int mat = nb >> 3;                   // 0=g1, 1=dre, 2=dim
    const int s = (nb >> 1) & 3;
    const int dbase = (nb & 1) * 128;

    const __half* gA = xh_g + (size_t)mbase * DIN;
    const __half* gB = w1f16_g + ((size_t)(mat * 4 + s) * DSZ + dbase) * DIN;

    float acc[2][8][4];
    gemm_pipeline<DIN / KCH>(gA, gB, DIN, s0, acc);

    const int lane = threadIdx.x & 31, warp = threadIdx.x >> 5;
    const int wm = warp & 3, wn = warp >> 2;
    const int r0 = mbase + wm * 32 + (lane >> 2);
    const int c0 = wn * 64 + (lane & 3) * 2;
    const float* bias = (mat == 0 ? bg1 : (mat == 1 ? bdr : bdi)) + s * DSZ + dbase;
    __half* op = (mat == 0 ? g1f16_g : (mat == 1 ? dre_g : dim_g)) + (size_t)s * MTOT * DSZ;
    const bool rl = (mat == 0);

#pragma unroll
    for (int mi = 0; mi < 2; mi++)
#pragma unroll
        for (int nf = 0; nf < 8; nf++) {
            int col = c0 + nf * 8;
            float b0 = bias[col], b1 = bias[col + 1];
#pragma unroll
            for (int hh = 0; hh < 2; hh++) {
                int r = r0 + mi * 16 + hh * 8;
                float v0 = acc[mi][nf][hh * 2 + 0] + b0;
                float v1 = acc[mi][nf][hh * 2 + 1] + b1;
                if (rl) { v0 = fmaxf(v0, 0.f); v1 = fmaxf(v1, 0.f); }
                *(__half2*)(op + (size_t)r * DSZ + dbase + col) =
                    __halves2half2(__float2half_rn(v0), __float2half_rn(v1));
            }
        }
}

// ---------------- GEMM 2: omg = 1 - sigmoid(g1 @ Wg2 + bg2) --------------------
__global__ __launch_bounds__(256) void gemm2_k(const float* __restrict__ bg2)
{
    extern __shared__ char sm[];
    uint32_t s0 = smem_u32(sm);

    const int mbase = blockIdx.x * 128;
    const int s = blockIdx.y >> 1;
    const int dbase = (blockIdx.y & 1) * 128;

    const __half* gA = g1f16_g + ((size_t)s * MTOT + mbase) * DSZ;
    const __half* gB = w2f16_g + ((size_t)s * DSZ + dbase) * DSZ;

    float acc[2][8][4];
    gemm_pipeline<DSZ / KCH>(gA, gB, DSZ, s0, acc);

    const int lane = threadIdx.x & 31, warp = threadIdx.x >> 5;
    const int wm = warp & 3, wn = warp >> 2;
    const int r0 = mbase + wm * 32 + (lane >> 2);
    const int c0 = wn * 64 + (lane & 3) * 2;
    const float* bias = bg2 + s * DSZ + dbase;
    float* op = omg_g + (size_t)s * MTOT * DSZ;

#pragma unroll
    for (int mi = 0; mi < 2; mi++)
#pragma unroll
        for (int nf = 0; nf < 8; nf++) {
            int col = c0 + nf * 8;
            float b0 = bias[col], b1 = bias[col + 1];
#pragma unroll
            for (int hh = 0; hh < 2; hh++) {
                int r = r0 + mi * 16 + hh * 8;
                float2 v;
                v.x = 1.0f / (1.0f + expf(acc[mi][nf][hh * 2 + 0] + b0));
                v.y = 1.0f / (1.0f + expf(acc[mi][nf][hh * 2 + 1] + b1));
                *(float2*)(op + (size_t)r * DSZ + dbase + col) = v;
            }
        }
}

// ---------------- conversion kernels -------------------------------------------
__global__ __launch_bounds__(256) void conv_x_k(const float* __restrict__ x) {
    size_t i = ((size_t)blockIdx.x * 256 + threadIdx.x) * 4;
    float4 v = *(const float4*)(x + i);
    union { __half h[4]; uint2 u; } p;
    p.h[0] = __float2half_rn(v.x);
    p.h[1] = __float2half_rn(v.y);
    p.h[2] = __float2half_rn(v.z);
    p.h[3] = __float2half_rn(v.w);
    *(uint2*)(xh_g + i) = p.u;
}

__global__ void conv_w1_k(const float* __restrict__ src, int zbase, int kdim) {
    __shared__ float t[32][33];
    int z = blockIdx.z;
    const float* sp = src + (size_t)z * kdim * DSZ;
    int tx = threadIdx.x, ty = threadIdx.y;
    int k0 = blockIdx.x * 32, d0 = blockIdx.y * 32;
#pragma unroll
    for (int i = 0; i < 4; i++)
        t[ty + i * 8][tx] = sp[(size_t)(k0 + ty + i * 8) * DSZ + d0 + tx];
    __syncthreads();
    __half* oh = (kdim == DIN ? w1f16_g + (size_t)(zbase + z) * DSZ * DIN
                              : w2f16_g + (size_t)z * DSZ * DSZ);
#pragma unroll
    for (int i = 0; i < 4; i++) {
        int n = d0 + ty + i * 8, k = k0 + tx;
        oh[(size_t)n * kdim + k] = __float2half_rn(t[tx][ty + i * 8]);
    }
}

// ---------------- segmented scan (3 phases) ------------------------------------
struct ScanConsts { float abr[4], abi[4], bsc[4]; };

__global__ __launch_bounds__(256) void scan_p1(ScanConsts c) {
    const int idx = blockIdx.x;                 // b*64 + s*16 + seg
    const int seg = idx & 15, s = (idx >> 4) & 3, b = idx >> 6;
    const int d = threadIdx.x;
    const float abr = c.abr[s], abi = c.abi[s], bs = c.bsc[s];
    const size_t base = ((size_t)s * MTOT + (size_t)b * 4096 + seg * 256) * DSZ + d;
    float Ar = 1.f, Ai = 0.f, Hr = 0.f, Hi = 0.f;
#pragma unroll 4
    for (int t = 0; t < 256; t++) {
        size_t off = base + (size_t)t * DSZ;
        float w  = omg_g[off];
        float xr = __half2float(dre_g[off]);
        float xi = __half2float(dim_g[off]);
        float ar = w * abr, ai = w * abi, wb = w * bs;
        float br = wb * xr, bi = wb * xi;
        float nHr = fmaf(ar, Hr, fmaf(-ai, Hi, br));
        float nHi = fmaf(ar, Hi, fmaf( ai, Hr, bi));
        float nAr = fmaf(ar, Ar, -ai * Ai);
        float nAi = fmaf(ar, Ai,  ai * Ar);
        Hr = nHr; Hi = nHi; Ar = nAr; Ai = nAi;
    }
    Aseg_g[idx * 256 + d] = make_float2(Ar, Ai);
    Hseg_g[idx * 256 + d] = make_float2(Hr, Hi);
}

__global__ __launch_bounds__(256) void scan_p2() {
    const int bs_ = blockIdx.x;                 // b*4 + s
    const int d = threadIdx.x;
    float cr = 0.f, ci = 0.f;
#pragma unroll
    for (int g = 0; g < 16; g++) {
        int idx = (bs_ * 16 + g) * 256 + d;
        Ini_g[idx] = make_float2(cr, ci);
        float2 A = Aseg_g[idx];
        float2 H = Hseg_g[idx];
        float ncr = fmaf(A.x, cr, fmaf(-A.y, ci, H.x));
        float nci = fmaf(A.x, ci, fmaf( A.y, cr, H.y));
        cr = ncr; ci = nci;
    }
}

__global__ __launch_bounds__(256) void scan_p3(float* __restrict__ out, ScanConsts c) {
    const int idx = blockIdx.x;
    const int seg = idx & 15, s = (idx >> 4) & 3, b = idx >> 6;
    const int d = threadIdx.x;
    const float abr = c.abr[s], abi = c.abi[s], bs = c.bsc[s];
    const size_t base = ((size_t)s * MTOT + (size_t)b * 4096 + seg * 256) * DSZ + d;
    float2 h0 = Ini_g[idx * 256 + d];
    float hr = h0.x, hi = h0.y;
    float* op = out + ((size_t)b * 4096 + seg * 256) * 2048 + (size_t)s * 512 + d;
#pragma unroll 4
    for (int t = 0; t < 256; t++) {
        size_t off = base + (size_t)t * DSZ;
        float w  = omg_g[off];
        float xr = __half2float(dre_g[off]);
        float xi = __half2float(dim_g[off]);
        float ar = w * abr, ai = w * abi, wb = w * bs;
        float br = wb * xr, bi = wb * xi;
        float nhr = fmaf(ar, hr, fmaf(-ai, hi, br));
        float nhi = fmaf(ar, hi, fmaf( ai, hr, bi));
        hr = nhr; hi = nhi;
        op[(size_t)t * 2048]       = hr;
        op[(size_t)t * 2048 + 256] = hi;
    }
}

// ---------------- host ----------------------------------------------------------
extern "C" void kernel_launch(void* const* d_in, const int* in_sizes, int n_in,
                              void* d_out, int out_size)
{
    const float* x   = (const float*)d_in[0];
    const float* Wg1 = (const float*)d_in[1];
    const float* bg1 = (const float*)d_in[2];
    const float* Wg2 = (const float*)d_in[3];
    const float* bg2 = (const float*)d_in[4];
    const float* Wdr = (const float*)d_in[5];
    const float* bdr = (const float*)d_in[6];
    const float* Wdi = (const float*)d_in[7];
    const float* bdi = (const float*)d_in[8];
    float* out = (float*)d_out;

    cudaFuncSetAttribute(gemm1_k, cudaFuncAttributeMaxDynamicSharedMemorySize, SMEM_SZ);
    cudaFuncSetAttribute(gemm2_k, cudaFuncAttributeMaxDynamicSharedMemorySize, SMEM_SZ);

    conv_x_k<<<(int)(((size_t)MTOT * DIN) / 1024), 256>>>(x);
    dim3 tb(32, 8);
    conv_w1_k<<<dim3(32, 8, 4), tb>>>(Wg1, 0, DIN);
    conv_w1_k<<<dim3(32, 8, 4), tb>>>(Wdr, 4, DIN);
    conv_w1_k<<<dim3(32, 8, 4), tb>>>(Wdi, 8, DIN);
    conv_w1_k<<<dim3(8, 8, 4), tb>>>(Wg2, 0, DSZ);

    gemm1_k<<<dim3(MTOT / 128, 24), 256, SMEM_SZ>>>(bg1, bdr, bdi);
    gemm2_k<<<dim3(MTOT / 128, 8), 256, SMEM_SZ>>>(bg2);

    ScanConsts c;
    const double r [4] = {1.0, 0.999, 0.9495, 0.9};
    const double th[4] = {0.0, 0.01,  0.505,  1.0};
    for (int s = 0; s < 4; s++) {
        c.abr[s] = (float)(r[s] * cos(th[s]));
        c.abi[s] = (float)(r[s] * sin(th[s]));
        c.bsc[s] = (float)((r[s] >= 1.0) ? (1.0 / 16.0) : (1.0 - r[s]));
    }
    scan_p1<<<256, 256>>>(c);
    scan_p2<<<16, 256>>>();
    scan_p3<<<256, 256>>>(out, c);
}

// round 7
// speedup vs baseline: 1.2157x; 1.0601x over previous
#include <cuda_runtime.h>
#include <cuda_fp16.h>
#include <stdint.h>
#include <math.h>

#define MTOT 16384
#define DIN  1024
#define DSZ  256
#define KCH  64            // k-halfs per pipeline chunk (128B data/row)
#define LDR  144           // padded SMEM row stride in bytes (128 data + 16 pad)
#define PL   (128 * LDR)   // 18432 bytes per plane (128 rows)
#define STG  (2 * PL)      // A, B planes per stage = 36864
#define NST  2
#define SMEM_SZ (NST * STG)   // 73728 -> 2 CTAs/SM

// ---------------- scratch (__device__ globals; no allocations) ----------------
__device__ __half xh_g[(size_t)MTOT * DIN];
__device__ __half w1f16_g[(size_t)12 * DSZ * DIN];   // [mat*4+s][n=d][k]
__device__ __half w2f16_g[(size_t)4 * DSZ * DSZ];    // [s][n=e][k]
__device__ __half g1f16_g[(size_t)4 * MTOT * DSZ];
__device__ __half dre_g[(size_t)4 * MTOT * DSZ];
__device__ __half dim_g[(size_t)4 * MTOT * DSZ];
__device__ float omg_g[(size_t)4 * MTOT * DSZ];
__device__ float2 Aseg_g[256 * 256];
__device__ float2 Hseg_g[256 * 256];
__device__ float2 Ini_g [256 * 256];

// ---------------- PTX helpers (baseline ISA only) ------------------------------
__device__ __forceinline__ uint32_t smem_u32(const void* p) {
    uint32_t a;
    asm("{ .reg .u64 t; cvta.to.shared.u64 t, %1; cvt.u32.u64 %0, t; }" : "=r"(a) : "l"(p));
    return a;
}
__device__ __forceinline__ void cpa16(uint32_t dst, const void* src) {
    asm volatile("cp.async.cg.shared.global [%0], [%1], 16;" :: "r"(dst), "l"(src));
}
__device__ __forceinline__ void cpa_commit() {
    asm volatile("cp.async.commit_group;");
}
template<int N> __device__ __forceinline__ void cpa_wait() {
    asm volatile("cp.async.wait_group %0;" :: "n"(N));
}
__device__ __forceinline__ void ldsm4(uint32_t r[4], uint32_t addr) {
    asm volatile("ldmatrix.sync.aligned.m8n8.x4.shared.b16 {%0,%1,%2,%3}, [%4];"
        : "=r"(r[0]), "=r"(r[1]), "=r"(r[2]), "=r"(r[3]) : "r"(addr));
}
__device__ __forceinline__ void mma_f16(float c[4], const uint32_t a[4], const uint32_t b[2]) {
    asm volatile("mma.sync.aligned.m16n8k16.row.col.f32.f16.f16.f32 "
        "{%0,%1,%2,%3}, {%4,%5,%6,%7}, {%8,%9}, {%0,%1,%2,%3};"
        : "+f"(c[0]), "+f"(c[1]), "+f"(c[2]), "+f"(c[3])
        : "r"(a[0]), "r"(a[1]), "r"(a[2]), "r"(a[3]), "r"(b[0]), "r"(b[1]));
}

// ---------------- GEMM pipeline core (128x128 tile, KCH=64, double buffer) ------
// 8 warps (4m x 2n). Per iter: wait<0>; sync; issue(ch+1); compute(ch).
template<int NCH>
__device__ __forceinline__ void gemm_pipeline(
    const __half* __restrict__ gA, const __half* __restrict__ gB,
    const int ldk, uint32_t s0, float acc[2][8][4])
{
    const int tid = threadIdx.x;

    auto issue = [&](int st, int k0) {
        uint32_t base = s0 + st * STG;
#pragma unroll
        for (int it = 0; it < 4; it++) {
            int q = tid + it * 256;
            int r = q >> 3, c = q & 7;
            uint32_t off = base + r * LDR + c * 16;
            size_t go = (size_t)r * ldk + k0 + c * 8;
            cpa16(off,      gA + go);
            cpa16(off + PL, gB + go);
        }
        cpa_commit();
    };

#pragma unroll
    for (int i = 0; i < 2; i++)
#pragma unroll
        for (int j = 0; j < 8; j++)
#pragma unroll
            for (int k = 0; k < 4; k++) acc[i][j][k] = 0.f;

    issue(0, 0);

    const int lane = tid & 31, warp = tid >> 5;
    const int wm = warp & 3, wn = warp >> 2;
    const uint32_t aBase = (uint32_t)(wm * 32 + (lane & 15)) * LDR + (lane >> 4) * 16;
    const uint32_t bBase = (uint32_t)(wn * 64 + (lane & 7) + ((lane & 16) >> 1)) * LDR
                         + ((lane >> 3) & 1) * 16;

    for (int ch = 0; ch < NCH; ch++) {
        cpa_wait<0>();
        __syncthreads();        // all threads' group-ch data visible; prev buf free
        if (ch + 1 < NCH) issue((ch + 1) & 1, (ch + 1) * KCH);
        const uint32_t sb = s0 + (ch & 1) * STG;
#pragma unroll
        for (int ks = 0; ks < 4; ks++) {
            uint32_t ah[2][4], bb[4][4];
#pragma unroll
            for (int mi = 0; mi < 2; mi++)
                ldsm4(ah[mi], sb + aBase + mi * (16 * LDR) + ks * 32);
#pragma unroll
            for (int nf4 = 0; nf4 < 4; nf4++)
                ldsm4(bb[nf4], sb + PL + bBase + nf4 * (16 * LDR) + ks * 32);
#pragma unroll
            for (int mi = 0; mi < 2; mi++)
#pragma unroll
                for (int nf = 0; nf < 8; nf++)
                    mma_f16(acc[mi][nf], ah[mi], &bb[nf >> 1][(nf & 1) * 2]);
        }
    }
}

// ---------------- GEMM 1: x @ {Wg1,Wdr,Wdi} -----------------------------------
__global__ __launch_bounds__(256) void gemm1_k(
    const float* __restrict__ bg1, const float* __restrict__ bdr, const float* __restrict__ bdi)
{
    extern __shared__ char sm[];
    uint32_t s0 = smem_u32(sm);

    const int mbase = blockIdx.x * 128;
    const int nb = blockIdx.y;                 // 0..23
    const int mat = nb >> 3;                   // 0=g1, 1=dre, 2=dim
    const int s = (nb >> 1) & 3;
    const int dbase = (nb & 1) * 128;

    const __half* gA = xh_g + (size_t)mbase * DIN;
    const __half* gB = w1f16_g + ((size_t)(mat * 4 + s) * DSZ + dbase) * DIN;

    float acc[2][8][4];
    gemm_pipeline<DIN / KCH>(gA, gB, DIN, s0, acc);

    const int lane = threadIdx.x & 31, warp = threadIdx.x >> 5;
    const int wm = warp & 3, wn = warp >> 2;
    const int r0 = mbase + wm * 32 + (lane >> 2);
    const int c0 = wn * 64 + (lane & 3) * 2;
    const float* bias = (mat == 0 ? bg1 : (mat == 1 ? bdr : bdi)) + s * DSZ + dbase;
    __half* op = (mat == 0 ? g1f16_g : (mat == 1 ? dre_g : dim_g)) + (size_t)s * MTOT * DSZ;
    const bool rl = (mat == 0);

#pragma unroll
    for (int mi = 0; mi < 2; mi++)
#pragma unroll
        for (int nf = 0; nf < 8; nf++) {
            int col = c0 + nf * 8;
            float b0 = bias[col], b1 = bias[col + 1];
#pragma unroll
            for (int hh = 0; hh < 2; hh++) {
                int r = r0 + mi * 16 + hh * 8;
                float v0 = acc[mi][nf][hh * 2 + 0] + b0;
                float v1 = acc[mi][nf][hh * 2 + 1] + b1;
                if (rl) { v0 = fmaxf(v0, 0.f); v1 = fmaxf(v1, 0.f); }
                *(__half2*)(op + (size_t)r * DSZ + dbase + col) =
                    __halves2half2(__float2half_rn(v0), __float2half_rn(v1));
            }
        }
}

// ---------------- GEMM 2: omg = 1 - sigmoid(g1 @ Wg2 + bg2) --------------------
__global__ __launch_bounds__(256) void gemm2_k(const float* __restrict__ bg2)
{
    extern __shared__ char sm[];
    uint32_t s0 = smem_u32(sm);

    const int mbase = blockIdx.x * 128;
    const int s = blockIdx.y >> 1;
    const int dbase = (blockIdx.y & 1) * 128;

    const __half* gA = g1f16_g + ((size_t)s * MTOT + mbase) * DSZ;
    const __half* gB = w2f16_g + ((size_t)s * DSZ + dbase) * DSZ;

    float acc[2][8][4];
    gemm_pipeline<DSZ / KCH>(gA, gB, DSZ, s0, acc);

    const int lane = threadIdx.x & 31, warp = threadIdx.x >> 5;
    const int wm = warp & 3, wn = warp >> 2;
    const int r0 = mbase + wm * 32 + (lane >> 2);
    const int c0 = wn * 64 + (lane & 3) * 2;
    const float* bias = bg2 + s * DSZ + dbase;
    float* op = omg_g + (size_t)s * MTOT * DSZ;

#pragma unroll
    for (int mi = 0; mi < 2; mi++)
#pragma unroll
        for (int nf = 0; nf < 8; nf++) {
            int col = c0 + nf * 8;
            float b0 = bias[col], b1 = bias[col + 1];
#pragma unroll
            for (int hh = 0; hh < 2; hh++) {
                int r = r0 + mi * 16 + hh * 8;
                float2 v;
                v.x = 1.0f / (1.0f + expf(acc[mi][nf][hh * 2 + 0] + b0));
                v.y = 1.0f / (1.0f + expf(acc[mi][nf][hh * 2 + 1] + b1));
                *(float2*)(op + (size_t)r * DSZ + dbase + col) = v;
            }
        }
}

// ---------------- conversion kernels -------------------------------------------
__global__ __launch_bounds__(256) void conv_x_k(const float* __restrict__ x) {
    size_t i = ((size_t)blockIdx.x * 256 + threadIdx.x) * 4;
    float4 v = *(const float4*)(x + i);
    union { __half h[4]; uint2 u; } p;
    p.h[0] = __float2half_rn(v.x);
    p.h[1] = __float2half_rn(v.y);
    p.h[2] = __float2half_rn(v.z);
    p.h[3] = __float2half_rn(v.w);
    *(uint2*)(xh_g + i) = p.u;
}

// all three W1 matrices in one launch: z 0..11 (mat = z/4)
__global__ void conv_w1_all_k(const float* __restrict__ Wg1,
                              const float* __restrict__ Wdr,
                              const float* __restrict__ Wdi) {
    __shared__ float t[32][33];
    int z = blockIdx.z;
    const float* base = (z < 4 ? Wg1 : (z < 8 ? Wdr : Wdi));
    const float* sp = base + (size_t)(z & 3) * DIN * DSZ;
    int tx = threadIdx.x, ty = threadIdx.y;
    int k0 = blockIdx.x * 32, d0 = blockIdx.y * 32;
#pragma unroll
    for (int i = 0; i < 4; i++)
        t[ty + i * 8][tx] = sp[(size_t)(k0 + ty + i * 8) * DSZ + d0 + tx];
    __syncthreads();
    __half* oh = w1f16_g + (size_t)z * DSZ * DIN;
#pragma unroll
    for (int i = 0; i < 4; i++) {
        int n = d0 + ty + i * 8, k = k0 + tx;
        oh[(size_t)n * DIN + k] = __float2half_rn(t[tx][ty + i * 8]);
    }
}

__global__ void conv_w2_k(const float* __restrict__ src) {
    __shared__ float t[32][33];
    int z = blockIdx.z;
    const float* sp = src + (size_t)z * DSZ * DSZ;
    int tx = threadIdx.x, ty = threadIdx.y;
    int k0 = blockIdx.x * 32, d0 = blockIdx.y * 32;
#pragma unroll
    for (int i = 0; i < 4; i++)
        t[ty + i * 8][tx] = sp[(size_t)(k0 + ty + i * 8) * DSZ + d0 + tx];
    __syncthreads();
    __half* oh = w2f16_g + (size_t)z * DSZ * DSZ;
#pragma unroll
    for (int i = 0; i < 4; i++) {
        int n = d0 + ty + i * 8, k = k0 + tx;
        oh[(size_t)n * DSZ + k] = __float2half_rn(t[tx][ty + i * 8]);
    }
}

// ---------------- segmented scan (3 phases) ------------------------------------
struct ScanConsts { float abr[4], abi[4], bsc[4]; };

__global__ __launch_bounds__(256) void scan_p1(ScanConsts c) {
    const int idx = blockIdx.x;                 // b*64 + s*16 + seg
    const int seg = idx & 15, s = (idx >> 4) & 3, b = idx >> 6;
    const int d = threadIdx.x;
    const float abr = c.abr[s], abi = c.abi[s], bs = c.bsc[s];
    const size_t base = ((size_t)s * MTOT + (size_t)b * 4096 + seg * 256) * DSZ + d;
    float Ar = 1.f, Ai = 0.f, Hr = 0.f, Hi = 0.f;
#pragma unroll 4
    for (int t = 0; t < 256; t++) {
        size_t off = base + (size_t)t * DSZ;
        float w  = omg_g[off];
        float xr = __half2float(dre_g[off]);
        float xi = __half2float(dim_g[off]);
        float ar = w * abr, ai = w * abi, wb = w * bs;
        float br = wb * xr, bi = wb * xi;
        float nHr = fmaf(ar, Hr, fmaf(-ai, Hi, br));
        float nHi = fmaf(ar, Hi, fmaf( ai, Hr, bi));
        float nAr = fmaf(ar, Ar, -ai * Ai);
        float nAi = fmaf(ar, Ai,  ai * Ar);
        Hr = nHr; Hi = nHi; Ar = nAr; Ai = nAi;
    }
    Aseg_g[idx * 256 + d] = make_float2(Ar, Ai);
    Hseg_g[idx * 256 + d] = make_float2(Hr, Hi);
}

__global__ __launch_bounds__(256) void scan_p2() {
    const int bs_ = blockIdx.x;                 // b*4 + s
    const int d = threadIdx.x;
    float cr = 0.f, ci = 0.f;
#pragma unroll
    for (int g = 0; g < 16; g++) {
        int idx = (bs_ * 16 + g) * 256 + d;
        Ini_g[idx] = make_float2(cr, ci);
        float2 A = Aseg_g[idx];
        float2 H = Hseg_g[idx];
        float ncr = fmaf(A.x, cr, fmaf(-A.y, ci, H.x));
        float nci = fmaf(A.x, ci, fmaf( A.y, cr, H.y));
        cr = ncr; ci = nci;
    }
}

__global__ __launch_bounds__(256) void scan_p3(float* __restrict__ out, ScanConsts c) {
    const int idx = blockIdx.x;
    const int seg = idx & 15, s = (idx >> 4) & 3, b = idx >> 6;
    const int d = threadIdx.x;
    const float abr = c.abr[s], abi = c.abi[s], bs = c.bsc[s];
    const size_t base = ((size_t)s * MTOT + (size_t)b * 4096 + seg * 256) * DSZ + d;
    float2 h0 = Ini_g[idx * 256 + d];
    float hr = h0.x, hi = h0.y;
    float* op = out + ((size_t)b * 4096 + seg * 256) * 2048 + (size_t)s * 512 + d;
#pragma unroll 4
    for (int t = 0; t < 256; t++) {
        size_t off = base + (size_t)t * DSZ;
        float w  = omg_g[off];
        float xr = __half2float(dre_g[off]);
        float xi = __half2float(dim_g[off]);
        float ar = w * abr, ai = w * abi, wb = w * bs;
        float br = wb * xr, bi = wb * xi;
        float nhr = fmaf(ar, hr, fmaf(-ai, hi, br));
        float nhi = fmaf(ar, hi, fmaf( ai, hr, bi));
        hr = nhr; hi = nhi;
        op[(size_t)t * 2048]       = hr;
        op[(size_t)t * 2048 + 256] = hi;
    }
}

// ---------------- host ----------------------------------------------------------
extern "C" void kernel_launch(void* const* d_in, const int* in_sizes, int n_in,
                              void* d_out, int out_size)
{
    const float* x   = (const float*)d_in[0];
    const float* Wg1 = (const float*)d_in[1];
    const float* bg1 = (const float*)d_in[2];
    const float* Wg2 = (const float*)d_in[3];
    const float* bg2 = (const float*)d_in[4];
    const float* Wdr = (const float*)d_in[5];
    const float* bdr = (const float*)d_in[6];
    const float* Wdi = (const float*)d_in[7];
    const float* bdi = (const float*)d_in[8];
    float* out = (float*)d_out;

    cudaFuncSetAttribute(gemm1_k, cudaFuncAttributeMaxDynamicSharedMemorySize, SMEM_SZ);
    cudaFuncSetAttribute(gemm2_k, cudaFuncAttributeMaxDynamicSharedMemorySize, SMEM_SZ);

    conv_x_k<<<(int)(((size_t)MTOT * DIN) / 1024), 256>>>(x);
    dim3 tb(32, 8);
    conv_w1_all_k<<<dim3(32, 8, 12), tb>>>(Wg1, Wdr, Wdi);
    conv_w2_k<<<dim3(8, 8, 4), tb>>>(Wg2);

    gemm1_k<<<dim3(MTOT / 128, 24), 256, SMEM_SZ>>>(bg1, bdr, bdi);
    gemm2_k<<<dim3(MTOT / 128, 8), 256, SMEM_SZ>>>(bg2);

    ScanConsts c;
    const double r [4] = {1.0, 0.999, 0.9495, 0.9};
    const double th[4] = {0.0, 0.01,  0.505,  1.0};
    for (int s = 0; s < 4; s++) {
        c.abr[s] = (float)(r[s] * cos(th[s]));
        c.abi[s] = (float)(r[s] * sin(th[s]));
        c.bsc[s] = (float)((r[s] >= 1.0) ? (1.0 / 16.0) : (1.0 - r[s]));
    }
    scan_p1<<<256, 256>>>(c);
    scan_p2<<<16, 256>>>();
    scan_p3<<<256, 256>>>(out, c);
}